// round 1
// baseline (speedup 1.0000x reference)
#include <cuda_runtime.h>

#define BATCH 4096
#define DIM 128
#define NROWS (2 * BATCH)          // 8192
#define BM 128
#define BN 128
#define KSPLIT 2
#define NTILES (NROWS / BN / KSPLIT)   // 32 key tiles per split
#define PAD_F4 33                  // smem row stride in float4 (132 floats)

// Scratch (no device allocation allowed -> __device__ globals)
__device__ float g_reps[NROWS * DIM];     // normalized [z_i; z_j], row-major
__device__ float g_pos[BATCH];            // dot(z_i, z_j) per pair
__device__ float g_part[KSPLIT * NROWS];  // partial exp-rowsums

// ---------------------------------------------------------------------------
// Kernel 1: row-normalize both projections, write reps, compute positives.
// One 128-thread block per batch row; 3 fused reductions (|a|^2, |b|^2, a.b).
// ---------------------------------------------------------------------------
__global__ void __launch_bounds__(128) normalize_kernel(const float* __restrict__ p1,
                                                        const float* __restrict__ p2) {
    int b = blockIdx.x;
    int t = threadIdx.x;
    float v1 = p1[b * DIM + t];
    float v2 = p2[b * DIM + t];
    float s11 = v1 * v1, s22 = v2 * v2, s12 = v1 * v2;
#pragma unroll
    for (int o = 16; o > 0; o >>= 1) {
        s11 += __shfl_xor_sync(0xffffffffu, s11, o);
        s22 += __shfl_xor_sync(0xffffffffu, s22, o);
        s12 += __shfl_xor_sync(0xffffffffu, s12, o);
    }
    __shared__ float sh[3][4];
    int w = t >> 5;
    if ((t & 31) == 0) { sh[0][w] = s11; sh[1][w] = s22; sh[2][w] = s12; }
    __syncthreads();
    s11 = sh[0][0] + sh[0][1] + sh[0][2] + sh[0][3];
    s22 = sh[1][0] + sh[1][1] + sh[1][2] + sh[1][3];
    s12 = sh[2][0] + sh[2][1] + sh[2][2] + sh[2][3];
    float n1 = fmaxf(sqrtf(s11), 1e-12f);
    float n2 = fmaxf(sqrtf(s22), 1e-12f);
    g_reps[b * DIM + t] = v1 / n1;
    g_reps[(BATCH + b) * DIM + t] = v2 / n2;
    if (t == 0) g_pos[b] = s12 / (n1 * n2);
}

// ---------------------------------------------------------------------------
// Kernel 2: for a 128-row block and one key split, accumulate
//   rowsum_i = sum_j exp(2 * dot(reps_i, reps_j))  over this split's 4096 keys.
// 256 threads, 8x8 micro-tile per thread with cyclic row/col assignment
// (rows ty+16i, cols tx+16j) -> smem micro-loads are broadcast / near
// conflict-free without any transpose. Gmem loads coalesced, STS.128 clean.
// ---------------------------------------------------------------------------
extern __shared__ float dyn_smem[];

__global__ void __launch_bounds__(256) simexp_kernel() {
    float4* As4 = (float4*)dyn_smem;              // BM rows x PAD_F4 float4
    float4* Bs4 = As4 + BM * PAD_F4;              // BN rows x PAD_F4 float4
    float*  red = (float*)(Bs4 + BN * PAD_F4);    // BM x 17

    const float4* reps4 = (const float4*)g_reps;  // [NROWS][32] float4

    int tid = threadIdx.x;
    int tx = tid & 15;       // 0..15 -> key columns tx + 16j
    int ty = tid >> 4;       // 0..15 -> query rows  ty + 16i
    int row0 = blockIdx.x * BM;
    int sp = blockIdx.y;

    // Load the query block once (stays resident across all key tiles).
#pragma unroll
    for (int it = 0; it < 16; ++it) {
        int idx = tid + it * 256;
        int m = idx >> 5, kg = idx & 31;                      // coalesced
        As4[m * PAD_F4 + kg] = reps4[(row0 + m) * 32 + kg];
    }

    float rowsum[8];
#pragma unroll
    for (int i = 0; i < 8; ++i) rowsum[i] = 0.f;

    for (int t = 0; t < NTILES; ++t) {
        int col0 = (sp * NTILES + t) * BN;
        __syncthreads();   // previous tile's compute done (and As ready at t=0)
#pragma unroll
        for (int it = 0; it < 16; ++it) {
            int idx = tid + it * 256;
            int m = idx >> 5, kg = idx & 31;
            Bs4[m * PAD_F4 + kg] = reps4[(col0 + m) * 32 + kg];
        }
        __syncthreads();

        float acc[8][8];
#pragma unroll
        for (int i = 0; i < 8; ++i)
#pragma unroll
            for (int j = 0; j < 8; ++j) acc[i][j] = 0.f;

#pragma unroll 2
        for (int k4 = 0; k4 < 32; ++k4) {
            float4 a4[8], b4[8];
#pragma unroll
            for (int i = 0; i < 8; ++i) a4[i] = As4[(ty + 16 * i) * PAD_F4 + k4];
#pragma unroll
            for (int j = 0; j < 8; ++j) b4[j] = Bs4[(tx + 16 * j) * PAD_F4 + k4];
#pragma unroll
            for (int i = 0; i < 8; ++i) {
#pragma unroll
                for (int j = 0; j < 8; ++j) {
                    acc[i][j] = fmaf(a4[i].x, b4[j].x, acc[i][j]);
                    acc[i][j] = fmaf(a4[i].y, b4[j].y, acc[i][j]);
                    acc[i][j] = fmaf(a4[i].z, b4[j].z, acc[i][j]);
                    acc[i][j] = fmaf(a4[i].w, b4[j].w, acc[i][j]);
                }
            }
        }

        // Fused epilogue: exp(sim / 0.5) and accumulate row sums (MUFU pipe,
        // hidden behind the FMA-bound mainloop).
#pragma unroll
        for (int i = 0; i < 8; ++i)
#pragma unroll
            for (int j = 0; j < 8; ++j)
                rowsum[i] += __expf(2.0f * acc[i][j]);
    }

    // Reduce the 16 tx-partials per row through smem.
#pragma unroll
    for (int i = 0; i < 8; ++i) red[(ty + 16 * i) * 17 + tx] = rowsum[i];
    __syncthreads();
    if (tid < BM) {
        float s = 0.f;
#pragma unroll
        for (int x = 0; x < 16; ++x) s += red[tid * 17 + x];
        g_part[sp * NROWS + row0 + tid] = s;
    }
}

// ---------------------------------------------------------------------------
// Kernel 3: loss = mean_i [ log(S_i - e^2) - 2 * pos_i ]
// (diagonal term sim_ii == 1 for normalized rows -> exp(2) subtracted exactly)
// ---------------------------------------------------------------------------
__global__ void __launch_bounds__(512) finalize_kernel(float* __restrict__ out) {
    const float E2 = 7.38905609893065f;  // exp(2)
    int tid = threadIdx.x;
    float s = 0.f;
    for (int i = tid; i < NROWS; i += 512) {
        float denom = g_part[i] + g_part[NROWS + i] - E2;
        float pos = g_pos[i & (BATCH - 1)];
        s += logf(denom) - 2.0f * pos;
    }
#pragma unroll
    for (int o = 16; o > 0; o >>= 1) s += __shfl_xor_sync(0xffffffffu, s, o);
    __shared__ float sh[16];
    if ((tid & 31) == 0) sh[tid >> 5] = s;
    __syncthreads();
    if (tid < 32) {
        float v = (tid < 16) ? sh[tid] : 0.f;
#pragma unroll
        for (int o = 8; o > 0; o >>= 1) v += __shfl_xor_sync(0xffffffffu, v, o);
        if (tid == 0) out[0] = v * (1.0f / (float)NROWS);
    }
}

// ---------------------------------------------------------------------------
extern "C" void kernel_launch(void* const* d_in, const int* in_sizes, int n_in,
                              void* d_out, int out_size) {
    const float* p1 = (const float*)d_in[0];
    const float* p2 = (const float*)d_in[1];
    float* out = (float*)d_out;

    normalize_kernel<<<BATCH, 128>>>(p1, p2);

    size_t smem_bytes = (size_t)(2 * BM * PAD_F4 * 4 + BM * 17) * sizeof(float); // 143,872 B
    cudaFuncSetAttribute((const void*)simexp_kernel,
                         cudaFuncAttributeMaxDynamicSharedMemorySize, (int)smem_bytes);
    simexp_kernel<<<dim3(NROWS / BM, KSPLIT), 256, smem_bytes>>>();

    finalize_kernel<<<1, 512>>>(out);
}

// round 6
// speedup vs baseline: 4.8943x; 4.8943x over previous
#include <cuda_runtime.h>
#include <cuda_bf16.h>
#include <cstdint>

#define BATCH 4096
#define DIM 128
#define NROWS (2 * BATCH)            // 8192
#define BM 128
#define BN 128
#define KSPLIT 2
#define NTILES (NROWS / BN / KSPLIT) // 32 key tiles per split

#define STRB 272                     // smem tile row stride in bytes (136 bf16)
#define SM_A 0
#define SM_B0 (128 * STRB)           // 34816
#define SM_B1 (SM_B0 + 128 * STRB)   // 69632
#define SM_RED (SM_B1 + 128 * STRB)  // 104448
#define SM_TOTAL (SM_RED + 256 * 4)  // 105472 bytes

// Scratch (device globals; no allocation allowed)
__device__ __align__(16) __nv_bfloat16 g_reps[NROWS * DIM]; // normalized rows, bf16
__device__ float g_pos[BATCH];             // exact fp32 dot(z_i, z_j)
__device__ float g_part[KSPLIT * NROWS];   // partial exp-rowsums

// ---------------------------------------------------------------------------
// helpers
// ---------------------------------------------------------------------------
__device__ __forceinline__ uint32_t smem_u32(const void* p) {
    uint32_t a;
    asm("{ .reg .u64 t; cvta.to.shared.u64 t, %1; cvt.u32.u64 %0, t; }"
        : "=r"(a) : "l"(p));
    return a;
}

__device__ __forceinline__ void ldsm4(uint32_t* r, uint32_t addr) {
    asm volatile("ldmatrix.sync.aligned.m8n8.x4.shared.b16 {%0,%1,%2,%3}, [%4];"
                 : "=r"(r[0]), "=r"(r[1]), "=r"(r[2]), "=r"(r[3]) : "r"(addr));
}

__device__ __forceinline__ void mma16816(float* c, const uint32_t* a,
                                         uint32_t b0, uint32_t b1) {
    asm volatile(
        "mma.sync.aligned.m16n8k16.row.col.f32.bf16.bf16.f32 "
        "{%0,%1,%2,%3}, {%4,%5,%6,%7}, {%8,%9}, {%0,%1,%2,%3};"
        : "+f"(c[0]), "+f"(c[1]), "+f"(c[2]), "+f"(c[3])
        : "r"(a[0]), "r"(a[1]), "r"(a[2]), "r"(a[3]), "r"(b0), "r"(b1));
}

// Prefetch a 128x128 bf16 tile (row-major, 256B rows) into smem rows of STRB
// bytes via cp.async (16B chunks, fully coalesced).
__device__ __forceinline__ void prefetch_tile(uint32_t sdst, const char* gsrc, int tid) {
#pragma unroll
    for (int it = 0; it < 8; ++it) {
        int idx = tid + it * 256;        // 0..2047
        int r = idx >> 4, s = idx & 15;
        uint32_t d = sdst + r * STRB + s * 16;
        const char* g = gsrc + r * 256 + s * 16;
        asm volatile("cp.async.cg.shared.global [%0], [%1], 16;"
                     :: "r"(d), "l"(g));
    }
}

// ---------------------------------------------------------------------------
// Kernel 1: normalize both projections -> bf16 reps; exact fp32 positives.
// ---------------------------------------------------------------------------
__global__ void __launch_bounds__(128) normalize_kernel(const float* __restrict__ p1,
                                                        const float* __restrict__ p2) {
    int b = blockIdx.x;
    int t = threadIdx.x;
    float v1 = p1[b * DIM + t];
    float v2 = p2[b * DIM + t];
    float s11 = v1 * v1, s22 = v2 * v2, s12 = v1 * v2;
#pragma unroll
    for (int o = 16; o > 0; o >>= 1) {
        s11 += __shfl_xor_sync(0xffffffffu, s11, o);
        s22 += __shfl_xor_sync(0xffffffffu, s22, o);
        s12 += __shfl_xor_sync(0xffffffffu, s12, o);
    }
    __shared__ float sh[3][4];
    int w = t >> 5;
    if ((t & 31) == 0) { sh[0][w] = s11; sh[1][w] = s22; sh[2][w] = s12; }
    __syncthreads();
    s11 = sh[0][0] + sh[0][1] + sh[0][2] + sh[0][3];
    s22 = sh[1][0] + sh[1][1] + sh[1][2] + sh[1][3];
    s12 = sh[2][0] + sh[2][1] + sh[2][2] + sh[2][3];
    float n1 = fmaxf(sqrtf(s11), 1e-12f);
    float n2 = fmaxf(sqrtf(s22), 1e-12f);
    g_reps[b * DIM + t] = __float2bfloat16(v1 / n1);
    g_reps[(BATCH + b) * DIM + t] = __float2bfloat16(v2 / n2);
    if (t == 0) g_pos[b] = s12 / (n1 * n2);
}

// ---------------------------------------------------------------------------
// Kernel 2: warp-mma bf16 sim + fused exp rowsum.
// CTA = 256 threads = 8 warps in 4(m) x 2(n); warp tile 32x64.
// A (query block) resident in smem; B (key tiles) double-buffered via cp.async.
// ---------------------------------------------------------------------------
extern __shared__ char sm[];

__global__ void __launch_bounds__(256, 1) simexp_mma_kernel() {
    const uint32_t sb = smem_u32(sm);
    const int tid = threadIdx.x;
    const int lane = tid & 31;
    const int wid = tid >> 5;
    const int wm = wid & 3;          // m chunk (32 rows)
    const int wn = wid >> 2;         // n chunk (64 cols)
    const int row0 = blockIdx.x * BM;
    const int sp = blockIdx.y;

    // prologue: prefetch A and first B tile in one group
    prefetch_tile(sb + SM_A, (const char*)(g_reps + (size_t)row0 * DIM), tid);
    prefetch_tile(sb + SM_B0,
                  (const char*)(g_reps + (size_t)(sp * NTILES) * BN * DIM), tid);
    asm volatile("cp.async.commit_group;" ::: "memory");

    const int lrow = lane & 15;
    const int lcol = (lane >> 4) * 16;   // byte offset within 16-elem k chunk
    const uint32_t a_base = sb + SM_A + (uint32_t)(wm * 32 + lrow) * STRB + lcol;

    float rowsum[4] = {0.f, 0.f, 0.f, 0.f};

    for (int t = 0; t < NTILES; ++t) {
        asm volatile("cp.async.wait_group 0;" ::: "memory");
        __syncthreads();
        if (t + 1 < NTILES) {
            uint32_t nb = sb + (((t + 1) & 1) ? SM_B1 : SM_B0);
            prefetch_tile(nb,
                (const char*)(g_reps + (size_t)(sp * NTILES + t + 1) * BN * DIM), tid);
            asm volatile("cp.async.commit_group;" ::: "memory");
        }
        const uint32_t b_base = sb + ((t & 1) ? SM_B1 : SM_B0)
                              + (uint32_t)(wn * 64 + lrow) * STRB + lcol;

        float acc[2][8][4];
#pragma unroll
        for (int i = 0; i < 2; ++i)
#pragma unroll
            for (int j = 0; j < 8; ++j)
#pragma unroll
                for (int q = 0; q < 4; ++q) acc[i][j][q] = 0.f;

#pragma unroll
        for (int ks = 0; ks < 8; ++ks) {
            uint32_t a[2][4];
            ldsm4(a[0], a_base + ks * 32);
            ldsm4(a[1], a_base + 16 * STRB + ks * 32);
#pragma unroll
            for (int p = 0; p < 4; ++p) {
                uint32_t b[4];
                ldsm4(b, b_base + (uint32_t)(p * 16) * STRB + ks * 32);
#pragma unroll
                for (int mt = 0; mt < 2; ++mt) {
                    mma16816(acc[mt][2 * p],     a[mt], b[0], b[2]);
                    mma16816(acc[mt][2 * p + 1], a[mt], b[1], b[3]);
                }
            }
        }

        // fused epilogue: exp(sim / 0.5), accumulate per-row partials
#pragma unroll
        for (int mt = 0; mt < 2; ++mt)
#pragma unroll
            for (int nt = 0; nt < 8; ++nt) {
                rowsum[mt * 2 + 0] += __expf(2.f * acc[mt][nt][0])
                                    + __expf(2.f * acc[mt][nt][1]);
                rowsum[mt * 2 + 1] += __expf(2.f * acc[mt][nt][2])
                                    + __expf(2.f * acc[mt][nt][3]);
            }
    }

    // reduce over the 4 n-lanes of each group, then across the 2 n-warps
#pragma unroll
    for (int r2 = 0; r2 < 4; ++r2) {
        rowsum[r2] += __shfl_xor_sync(0xffffffffu, rowsum[r2], 1);
        rowsum[r2] += __shfl_xor_sync(0xffffffffu, rowsum[r2], 2);
    }
    float* red = (float*)(sm + SM_RED);
    __syncthreads();
    if ((lane & 3) == 0) {
#pragma unroll
        for (int r2 = 0; r2 < 4; ++r2) {
            int row = wm * 32 + (r2 >> 1) * 16 + (r2 & 1) * 8 + (lane >> 2);
            red[row * 2 + wn] = rowsum[r2];
        }
    }
    __syncthreads();
    if (tid < BM)
        g_part[sp * NROWS + row0 + tid] = red[tid * 2] + red[tid * 2 + 1];
}

// ---------------------------------------------------------------------------
// Kernel 3: loss = mean_i [ log(S_i - e^2) - 2 * pos_i ]
// ---------------------------------------------------------------------------
__global__ void __launch_bounds__(512) finalize_kernel(float* __restrict__ out) {
    const float E2 = 7.38905609893065f;  // exp(2): diagonal of normalized sim
    int tid = threadIdx.x;
    float s = 0.f;
    for (int i = tid; i < NROWS; i += 512) {
        float denom = g_part[i] + g_part[NROWS + i] - E2;
        float pos = g_pos[i & (BATCH - 1)];
        s += logf(denom) - 2.0f * pos;
    }
#pragma unroll
    for (int o = 16; o > 0; o >>= 1) s += __shfl_xor_sync(0xffffffffu, s, o);
    __shared__ float sh[16];
    if ((tid & 31) == 0) sh[tid >> 5] = s;
    __syncthreads();
    if (tid < 32) {
        float v = (tid < 16) ? sh[tid] : 0.f;
#pragma unroll
        for (int o = 8; o > 0; o >>= 1) v += __shfl_xor_sync(0xffffffffu, v, o);
        if (tid == 0) out[0] = v * (1.0f / (float)NROWS);
    }
}

// ---------------------------------------------------------------------------
extern "C" void kernel_launch(void* const* d_in, const int* in_sizes, int n_in,
                              void* d_out, int out_size) {
    const float* p1 = (const float*)d_in[0];
    const float* p2 = (const float*)d_in[1];
    float* out = (float*)d_out;

    normalize_kernel<<<BATCH, 128>>>(p1, p2);

    cudaFuncSetAttribute((const void*)simexp_mma_kernel,
                         cudaFuncAttributeMaxDynamicSharedMemorySize, SM_TOTAL);
    simexp_mma_kernel<<<dim3(NROWS / BM, KSPLIT), 256, SM_TOTAL>>>();

    finalize_kernel<<<1, 512>>>(out);
}

// round 13
// speedup vs baseline: 6.1422x; 1.2550x over previous
#include <cuda_runtime.h>
#include <cuda_bf16.h>
#include <cstdint>

#define BATCH 4096
#define DIM 128
#define NROWS (2 * BATCH)            // 8192
#define BM 128
#define BN 128
#define NBLK (NROWS / BM)            // 64 row/col blocks
#define NT_TOTAL (NBLK * (NBLK + 1) / 2)  // 2080 upper-triangle tiles
#define NCTA 148

#define STRB 272                     // smem tile row stride in bytes (136 bf16)
#define SM_A0 0
#define SM_B0 34816
#define SM_A1 69632
#define SM_B1 104448
#define SM_REDR 139264               // 256 floats (row partials x 2 wn)
#define SM_REDC 140288               // 128*33 floats (col slot partials)
#define SM_TOTAL (SM_REDC + 128 * 33 * 4)  // 157184 bytes

// Scratch (device globals; no allocation allowed)
__device__ __align__(16) __nv_bfloat16 gx_reps[NROWS * DIM]; // normalized rows, bf16
__device__ float gx_pos[BATCH];               // exact fp32 dot(z_i, z_j)
__device__ float gx_slice[NCTA * NROWS];      // per-CTA exp-rowsum slices
__device__ float gx_part[NROWS];              // per-row loss terms

// ---------------------------------------------------------------------------
// helpers
// ---------------------------------------------------------------------------
__device__ __forceinline__ uint32_t smem_cast_u32(const void* p) {
    uint32_t a;
    asm("{ .reg .u64 t; cvta.to.shared.u64 t, %1; cvt.u32.u64 %0, t; }"
        : "=r"(a) : "l"(p));
    return a;
}

__device__ __forceinline__ void ldsm_x4(uint32_t* r, uint32_t addr) {
    asm volatile("ldmatrix.sync.aligned.m8n8.x4.shared.b16 {%0,%1,%2,%3}, [%4];"
                 : "=r"(r[0]), "=r"(r[1]), "=r"(r[2]), "=r"(r[3]) : "r"(addr));
}

__device__ __forceinline__ void mma_bf16_16816(float* c, const uint32_t* a,
                                               uint32_t b0, uint32_t b1) {
    asm volatile(
        "mma.sync.aligned.m16n8k16.row.col.f32.bf16.bf16.f32 "
        "{%0,%1,%2,%3}, {%4,%5,%6,%7}, {%8,%9}, {%0,%1,%2,%3};"
        : "+f"(c[0]), "+f"(c[1]), "+f"(c[2]), "+f"(c[3])
        : "r"(a[0]), "r"(a[1]), "r"(a[2]), "r"(a[3]), "r"(b0), "r"(b1));
}

// Map linear upper-triangle index -> (i, j), i <= j.  off(i) = i*(129-i)/2.
__device__ __forceinline__ void tri_index_map(int idx, int& io, int& jo) {
    float f = (129.0f - sqrtf(16641.0f - 8.0f * (float)idx)) * 0.5f;
    int i = (int)f;
    while (i > 0 && i * (129 - i) / 2 > idx) --i;
    while ((i + 1) * (128 - i) / 2 <= idx) ++i;
    io = i;
    jo = i + (idx - i * (129 - i) / 2);
}

// Prefetch tile pair (A = block i, B = block j) into buffer parity p.
__device__ __forceinline__ void prefetch_tiles(uint32_t sb, int p, int i, int j, int tid) {
    uint32_t abuf = sb + (p ? SM_A1 : SM_A0);
    uint32_t bbuf = sb + (p ? SM_B1 : SM_B0);
    const char* ga = (const char*)(gx_reps + (size_t)i * BM * DIM);
    const char* gb = (const char*)(gx_reps + (size_t)j * BN * DIM);
#pragma unroll
    for (int it = 0; it < 8; ++it) {
        int idx2 = tid + it * 256;       // 0..2047 (16B chunks)
        int r = idx2 >> 4, s = idx2 & 15;
        uint32_t off = (uint32_t)(r * STRB + s * 16);
        const char* g0 = ga + r * 256 + s * 16;
        const char* g1 = gb + r * 256 + s * 16;
        asm volatile("cp.async.cg.shared.global [%0], [%1], 16;"
                     :: "r"(abuf + off), "l"(g0));
        asm volatile("cp.async.cg.shared.global [%0], [%1], 16;"
                     :: "r"(bbuf + off), "l"(g1));
    }
}

// ---------------------------------------------------------------------------
// Kernel 1: normalize both projections -> bf16 reps; exact fp32 positives.
// ---------------------------------------------------------------------------
__global__ void __launch_bounds__(128) l2norm_pos_kernel(const float* __restrict__ p1,
                                                         const float* __restrict__ p2) {
    int b = blockIdx.x;
    int t = threadIdx.x;
    float v1 = p1[b * DIM + t];
    float v2 = p2[b * DIM + t];
    float s11 = v1 * v1, s22 = v2 * v2, s12 = v1 * v2;
#pragma unroll
    for (int o = 16; o > 0; o >>= 1) {
        s11 += __shfl_xor_sync(0xffffffffu, s11, o);
        s22 += __shfl_xor_sync(0xffffffffu, s22, o);
        s12 += __shfl_xor_sync(0xffffffffu, s12, o);
    }
    __shared__ float sh[3][4];
    int w = t >> 5;
    if ((t & 31) == 0) { sh[0][w] = s11; sh[1][w] = s22; sh[2][w] = s12; }
    __syncthreads();
    s11 = sh[0][0] + sh[0][1] + sh[0][2] + sh[0][3];
    s22 = sh[1][0] + sh[1][1] + sh[1][2] + sh[1][3];
    s12 = sh[2][0] + sh[2][1] + sh[2][2] + sh[2][3];
    float n1 = fmaxf(sqrtf(s11), 1e-12f);
    float n2 = fmaxf(sqrtf(s22), 1e-12f);
    gx_reps[b * DIM + t] = __float2bfloat16(v1 / n1);
    gx_reps[(BATCH + b) * DIM + t] = __float2bfloat16(v2 / n2);
    if (t == 0) gx_pos[b] = s12 / (n1 * n2);
}

// ---------------------------------------------------------------------------
// Kernel 2: persistent symmetric warp-mma sim + fused exp row/col sums.
// 148 CTAs loop over the 2080 upper-triangle 128x128 tiles. Per tile, exps
// are reduced along n (-> rows of block i) and along m (-> rows of block j,
// by symmetry). FIX vs R7/R9/R12: (i, j) now ADVANCE every iteration —
// previously the first tile's (i, j) was reused for all of a CTA's tiles
// (correct data, wrong attribution; the source of the bit-identical 6.1%).
// ---------------------------------------------------------------------------
extern __shared__ char smbuf[];

__global__ void __launch_bounds__(256, 1) simexp_tri_kernel() {
    const uint32_t sb = smem_cast_u32(smbuf);
    const int tid = threadIdx.x;
    const int lane = tid & 31;
    const int wid = tid >> 5;
    const int wm = wid & 3;          // m chunk (32 rows)
    const int wn = wid >> 2;         // n chunk (64 cols)
    const int cta = blockIdx.x;
    float* slice = gx_slice + (size_t)cta * NROWS;
    float* red_r = (float*)(smbuf + SM_REDR);
    float* red_c2 = (float*)(smbuf + SM_REDC);

    // zero this CTA's slice
    for (int k = tid; k < NROWS; k += 256) slice[k] = 0.f;

    const int lrow = lane & 15;
    const int lcol = (lane >> 4) * 16;
    const int slot = wm * 8 + (lane >> 2);   // unique row-slot for colsum cells

    int idx = cta;
    int i, j;
    tri_index_map(idx, i, j);
    prefetch_tiles(sb, 0, i, j, tid);
    asm volatile("cp.async.commit_group;" ::: "memory");

    int p = 0;
    for (; idx < NT_TOTAL; idx += NCTA, p ^= 1) {
        int ni = 0, nj = 0;
        const bool has_next = (idx + NCTA < NT_TOTAL);
        if (has_next) {
            tri_index_map(idx + NCTA, ni, nj);
            prefetch_tiles(sb, p ^ 1, ni, nj, tid);
            asm volatile("cp.async.commit_group;" ::: "memory");
            asm volatile("cp.async.wait_group 1;" ::: "memory");
        } else {
            asm volatile("cp.async.wait_group 0;" ::: "memory");
        }
        __syncthreads();   // tile ready; also guards red_r/red_c2 reuse

        const uint32_t a_base = sb + (p ? SM_A1 : SM_A0)
                              + (uint32_t)(wm * 32 + lrow) * STRB + lcol;
        const uint32_t b_base = sb + (p ? SM_B1 : SM_B0)
                              + (uint32_t)(wn * 64 + lrow) * STRB + lcol;

        float acc[2][8][4];
#pragma unroll
        for (int m = 0; m < 2; ++m)
#pragma unroll
            for (int n = 0; n < 8; ++n)
#pragma unroll
                for (int q = 0; q < 4; ++q) acc[m][n][q] = 0.f;

#pragma unroll
        for (int ks = 0; ks < 8; ++ks) {
            uint32_t a[2][4];
            ldsm_x4(a[0], a_base + ks * 32);
            ldsm_x4(a[1], a_base + 16 * STRB + ks * 32);
#pragma unroll
            for (int pp = 0; pp < 4; ++pp) {
                uint32_t b[4];
                ldsm_x4(b, b_base + (uint32_t)(pp * 16) * STRB + ks * 32);
#pragma unroll
                for (int mt = 0; mt < 2; ++mt) {
                    mma_bf16_16816(acc[mt][2 * pp],     a[mt], b[0], b[2]);
                    mma_bf16_16816(acc[mt][2 * pp + 1], a[mt], b[1], b[3]);
                }
            }
        }

        // exps in place
#pragma unroll
        for (int mt = 0; mt < 2; ++mt)
#pragma unroll
            for (int nt = 0; nt < 8; ++nt)
#pragma unroll
                for (int q = 0; q < 4; ++q)
                    acc[mt][nt][q] = __expf(2.f * acc[mt][nt][q]);

        // rowsum: reduce along n (cols) -> 4 row values/thread (R6-proven)
        float rowsum[4] = {0.f, 0.f, 0.f, 0.f};
#pragma unroll
        for (int mt = 0; mt < 2; ++mt)
#pragma unroll
            for (int nt = 0; nt < 8; ++nt) {
                rowsum[mt * 2 + 0] += acc[mt][nt][0] + acc[mt][nt][1];
                rowsum[mt * 2 + 1] += acc[mt][nt][2] + acc[mt][nt][3];
            }
#pragma unroll
        for (int r2 = 0; r2 < 4; ++r2) {
            rowsum[r2] += __shfl_xor_sync(0xffffffffu, rowsum[r2], 1);
            rowsum[r2] += __shfl_xor_sync(0xffffffffu, rowsum[r2], 2);
        }
        if ((lane & 3) == 0) {
#pragma unroll
            for (int r2 = 0; r2 < 4; ++r2) {
                int row = wm * 32 + (r2 >> 1) * 16 + (r2 & 1) * 8 + (lane >> 2);
                red_r[row * 2 + wn] = rowsum[r2];
            }
        }

        // colsum (skip on diag): fold the 4 same-column accumulators
        // (rows +0/+8/+16/+24 relative to lane>>2) and store to a unique cell.
        if (i != j) {
#pragma unroll
            for (int nt = 0; nt < 8; ++nt) {
#pragma unroll
                for (int j0 = 0; j0 < 2; ++j0) {
                    float v = acc[0][nt][j0] + acc[0][nt][j0 + 2]
                            + acc[1][nt][j0] + acc[1][nt][j0 + 2];
                    int col = wn * 64 + (nt >> 1) * 16 + (nt & 1) * 8
                            + (lane & 3) * 2 + j0;
                    red_c2[col * 33 + slot] = v;
                }
            }
        }
        __syncthreads();

        if (tid < BM) {
            slice[i * BM + tid] += red_r[tid * 2] + red_r[tid * 2 + 1];
            if (i != j) {
                float s = 0.f;
#pragma unroll
                for (int k = 0; k < 32; ++k) s += red_c2[tid * 33 + k];
                slice[j * BN + tid] += s;
            }
        }

        // advance tile coordinates (THE FIX)
        i = ni;
        j = nj;
        // loop-top __syncthreads guards red reuse
    }
}

// ---------------------------------------------------------------------------
// Kernel 3a: per-row term = log(sum_slices - e^2) - 2 * pos
// ---------------------------------------------------------------------------
__global__ void __launch_bounds__(512) rowterm2_kernel() {
    const float E2 = 7.38905609893065f;  // exp(2): diagonal of normalized sim
    int r = blockIdx.x * 512 + threadIdx.x;
    float s = 0.f;
#pragma unroll 4
    for (int c = 0; c < NCTA; ++c) s += gx_slice[(size_t)c * NROWS + r];
    gx_part[r] = logf(s - E2) - 2.0f * gx_pos[r & (BATCH - 1)];
}

// ---------------------------------------------------------------------------
// Kernel 3b: mean over 8192 rows
// ---------------------------------------------------------------------------
__global__ void __launch_bounds__(512) meanloss_kernel(float* __restrict__ out) {
    int tid = threadIdx.x;
    float s = 0.f;
    for (int r2 = tid; r2 < NROWS; r2 += 512) s += gx_part[r2];
#pragma unroll
    for (int o = 16; o > 0; o >>= 1) s += __shfl_xor_sync(0xffffffffu, s, o);
    __shared__ float sh[16];
    if ((tid & 31) == 0) sh[tid >> 5] = s;
    __syncthreads();
    if (tid < 32) {
        float v = (tid < 16) ? sh[tid] : 0.f;
#pragma unroll
        for (int o = 8; o > 0; o >>= 1) v += __shfl_xor_sync(0xffffffffu, v, o);
        if (tid == 0) out[0] = v * (1.0f / (float)NROWS);
    }
}

// ---------------------------------------------------------------------------
extern "C" void kernel_launch(void* const* d_in, const int* in_sizes, int n_in,
                              void* d_out, int out_size) {
    const float* p1 = (const float*)d_in[0];
    const float* p2 = (const float*)d_in[1];
    float* out = (float*)d_out;

    l2norm_pos_kernel<<<BATCH, 128>>>(p1, p2);

    cudaFuncSetAttribute((const void*)simexp_tri_kernel,
                         cudaFuncAttributeMaxDynamicSharedMemorySize, SM_TOTAL);
    simexp_tri_kernel<<<NCTA, 256, SM_TOTAL>>>();

    rowterm2_kernel<<<NROWS / 512, 512>>>();
    meanloss_kernel<<<1, 512>>>(out);
}

// round 14
// speedup vs baseline: 6.6942x; 1.0899x over previous
#include <cuda_runtime.h>
#include <cuda_bf16.h>
#include <cstdint>

#define BATCH 4096
#define DIM 128
#define NROWS (2 * BATCH)            // 8192
#define BM 128
#define BN 128
#define NBLK (NROWS / BM)            // 64 row/col blocks
#define NT_TOTAL (NBLK * (NBLK + 1) / 2)  // 2080 upper-triangle tiles
#define NCTA 148
#define NRBLK 16                     // rowterm grid

#define STRB 272                     // smem tile row stride in bytes (136 bf16)
#define SM_A0 0
#define SM_B0 34816
#define SM_A1 69632
#define SM_B1 104448
#define SM_REDR 139264               // 256 floats (row partials x 2 wn)
#define SM_REDC 140288               // 128*33 floats (col slot partials)
#define SM_TOTAL (SM_REDC + 128 * 33 * 4)  // 157184 bytes

// Scratch (device globals; no allocation allowed)
__device__ __align__(16) __nv_bfloat16 gx_reps[NROWS * DIM]; // normalized rows, bf16
__device__ float gx_pos[BATCH];               // exact fp32 dot(z_i, z_j)
__device__ float gx_slice[NCTA * NROWS];      // per-CTA exp-rowsum slices
__device__ float gx_bsum[NRBLK];              // rowterm block partials

// ---------------------------------------------------------------------------
// helpers
// ---------------------------------------------------------------------------
__device__ __forceinline__ uint32_t smem_cast_u32(const void* p) {
    uint32_t a;
    asm("{ .reg .u64 t; cvta.to.shared.u64 t, %1; cvt.u32.u64 %0, t; }"
        : "=r"(a) : "l"(p));
    return a;
}

__device__ __forceinline__ void ldsm_x4(uint32_t* r, uint32_t addr) {
    asm volatile("ldmatrix.sync.aligned.m8n8.x4.shared.b16 {%0,%1,%2,%3}, [%4];"
                 : "=r"(r[0]), "=r"(r[1]), "=r"(r[2]), "=r"(r[3]) : "r"(addr));
}

__device__ __forceinline__ void mma_bf16_16816(float* c, const uint32_t* a,
                                               uint32_t b0, uint32_t b1) {
    asm volatile(
        "mma.sync.aligned.m16n8k16.row.col.f32.bf16.bf16.f32 "
        "{%0,%1,%2,%3}, {%4,%5,%6,%7}, {%8,%9}, {%0,%1,%2,%3};"
        : "+f"(c[0]), "+f"(c[1]), "+f"(c[2]), "+f"(c[3])
        : "r"(a[0]), "r"(a[1]), "r"(a[2]), "r"(a[3]), "r"(b0), "r"(b1));
}

// Map linear upper-triangle index -> (i, j), i <= j.  off(i) = i*(129-i)/2.
__device__ __forceinline__ void tri_index_map(int idx, int& io, int& jo) {
    float f = (129.0f - sqrtf(16641.0f - 8.0f * (float)idx)) * 0.5f;
    int i = (int)f;
    while (i > 0 && i * (129 - i) / 2 > idx) --i;
    while ((i + 1) * (128 - i) / 2 <= idx) ++i;
    io = i;
    jo = i + (idx - i * (129 - i) / 2);
}

// Prefetch tile pair (A = block i, B = block j) into buffer parity p.
__device__ __forceinline__ void prefetch_tiles(uint32_t sb, int p, int i, int j, int tid) {
    uint32_t abuf = sb + (p ? SM_A1 : SM_A0);
    uint32_t bbuf = sb + (p ? SM_B1 : SM_B0);
    const char* ga = (const char*)(gx_reps + (size_t)i * BM * DIM);
    const char* gb = (const char*)(gx_reps + (size_t)j * BN * DIM);
#pragma unroll
    for (int it = 0; it < 8; ++it) {
        int idx2 = tid + it * 256;       // 0..2047 (16B chunks)
        int r = idx2 >> 4, s = idx2 & 15;
        uint32_t off = (uint32_t)(r * STRB + s * 16);
        const char* g0 = ga + r * 256 + s * 16;
        const char* g1 = gb + r * 256 + s * 16;
        asm volatile("cp.async.cg.shared.global [%0], [%1], 16;"
                     :: "r"(abuf + off), "l"(g0));
        asm volatile("cp.async.cg.shared.global [%0], [%1], 16;"
                     :: "r"(bbuf + off), "l"(g1));
    }
}

// ---------------------------------------------------------------------------
// Kernel 1: normalize both projections -> bf16 reps; exact fp32 positives.
// Warp-per-row: 256-thread block handles 8 rows; lane holds 4 elems (float4).
// ---------------------------------------------------------------------------
__global__ void __launch_bounds__(256) l2norm_pos_kernel(const float* __restrict__ p1,
                                                         const float* __restrict__ p2) {
    int w = threadIdx.x >> 5;
    int lane = threadIdx.x & 31;
    int b = blockIdx.x * 8 + w;                  // row 0..4095
    const float4* r1 = (const float4*)(p1 + (size_t)b * DIM);
    const float4* r2 = (const float4*)(p2 + (size_t)b * DIM);
    float4 v1 = r1[lane];
    float4 v2 = r2[lane];
    float s11 = v1.x * v1.x + v1.y * v1.y + v1.z * v1.z + v1.w * v1.w;
    float s22 = v2.x * v2.x + v2.y * v2.y + v2.z * v2.z + v2.w * v2.w;
    float s12 = v1.x * v2.x + v1.y * v2.y + v1.z * v2.z + v1.w * v2.w;
#pragma unroll
    for (int o = 16; o > 0; o >>= 1) {
        s11 += __shfl_xor_sync(0xffffffffu, s11, o);
        s22 += __shfl_xor_sync(0xffffffffu, s22, o);
        s12 += __shfl_xor_sync(0xffffffffu, s12, o);
    }
    float n1 = fmaxf(sqrtf(s11), 1e-12f);
    float n2 = fmaxf(sqrtf(s22), 1e-12f);
    float in1 = 1.0f / n1, in2 = 1.0f / n2;
    __nv_bfloat162 o1a = __floats2bfloat162_rn(v1.x * in1, v1.y * in1);
    __nv_bfloat162 o1b = __floats2bfloat162_rn(v1.z * in1, v1.w * in1);
    __nv_bfloat162 o2a = __floats2bfloat162_rn(v2.x * in2, v2.y * in2);
    __nv_bfloat162 o2b = __floats2bfloat162_rn(v2.z * in2, v2.w * in2);
    uint2* d1 = (uint2*)(gx_reps + (size_t)b * DIM);
    uint2* d2 = (uint2*)(gx_reps + (size_t)(BATCH + b) * DIM);
    uint2 u1, u2;
    u1.x = *(uint32_t*)&o1a; u1.y = *(uint32_t*)&o1b;
    u2.x = *(uint32_t*)&o2a; u2.y = *(uint32_t*)&o2b;
    d1[lane] = u1;
    d2[lane] = u2;
    if (lane == 0) gx_pos[b] = s12 * in1 * in2;
}

// ---------------------------------------------------------------------------
// Kernel 2: persistent symmetric warp-mma sim + fused exp row/col sums.
// (UNCHANGED from the 67.5us R13 kernel — validated at rel_err 0.0.)
// ---------------------------------------------------------------------------
extern __shared__ char smbuf[];

__global__ void __launch_bounds__(256, 1) simexp_tri_kernel() {
    const uint32_t sb = smem_cast_u32(smbuf);
    const int tid = threadIdx.x;
    const int lane = tid & 31;
    const int wid = tid >> 5;
    const int wm = wid & 3;          // m chunk (32 rows)
    const int wn = wid >> 2;         // n chunk (64 cols)
    const int cta = blockIdx.x;
    float* slice = gx_slice + (size_t)cta * NROWS;
    float* red_r = (float*)(smbuf + SM_REDR);
    float* red_c2 = (float*)(smbuf + SM_REDC);

    // zero this CTA's slice
    for (int k = tid; k < NROWS; k += 256) slice[k] = 0.f;

    const int lrow = lane & 15;
    const int lcol = (lane >> 4) * 16;
    const int slot = wm * 8 + (lane >> 2);   // unique row-slot for colsum cells

    int idx = cta;
    int i, j;
    tri_index_map(idx, i, j);
    prefetch_tiles(sb, 0, i, j, tid);
    asm volatile("cp.async.commit_group;" ::: "memory");

    int p = 0;
    for (; idx < NT_TOTAL; idx += NCTA, p ^= 1) {
        int ni = 0, nj = 0;
        const bool has_next = (idx + NCTA < NT_TOTAL);
        if (has_next) {
            tri_index_map(idx + NCTA, ni, nj);
            prefetch_tiles(sb, p ^ 1, ni, nj, tid);
            asm volatile("cp.async.commit_group;" ::: "memory");
            asm volatile("cp.async.wait_group 1;" ::: "memory");
        } else {
            asm volatile("cp.async.wait_group 0;" ::: "memory");
        }
        __syncthreads();   // tile ready; also guards red_r/red_c2 reuse

        const uint32_t a_base = sb + (p ? SM_A1 : SM_A0)
                              + (uint32_t)(wm * 32 + lrow) * STRB + lcol;
        const uint32_t b_base = sb + (p ? SM_B1 : SM_B0)
                              + (uint32_t)(wn * 64 + lrow) * STRB + lcol;

        float acc[2][8][4];
#pragma unroll
        for (int m = 0; m < 2; ++m)
#pragma unroll
            for (int n = 0; n < 8; ++n)
#pragma unroll
                for (int q = 0; q < 4; ++q) acc[m][n][q] = 0.f;

#pragma unroll
        for (int ks = 0; ks < 8; ++ks) {
            uint32_t a[2][4];
            ldsm_x4(a[0], a_base + ks * 32);
            ldsm_x4(a[1], a_base + 16 * STRB + ks * 32);
#pragma unroll
            for (int pp = 0; pp < 4; ++pp) {
                uint32_t b[4];
                ldsm_x4(b, b_base + (uint32_t)(pp * 16) * STRB + ks * 32);
#pragma unroll
                for (int mt = 0; mt < 2; ++mt) {
                    mma_bf16_16816(acc[mt][2 * pp],     a[mt], b[0], b[2]);
                    mma_bf16_16816(acc[mt][2 * pp + 1], a[mt], b[1], b[3]);
                }
            }
        }

        // exps in place
#pragma unroll
        for (int mt = 0; mt < 2; ++mt)
#pragma unroll
            for (int nt = 0; nt < 8; ++nt)
#pragma unroll
                for (int q = 0; q < 4; ++q)
                    acc[mt][nt][q] = __expf(2.f * acc[mt][nt][q]);

        // rowsum: reduce along n (cols) -> 4 row values/thread
        float rowsum[4] = {0.f, 0.f, 0.f, 0.f};
#pragma unroll
        for (int mt = 0; mt < 2; ++mt)
#pragma unroll
            for (int nt = 0; nt < 8; ++nt) {
                rowsum[mt * 2 + 0] += acc[mt][nt][0] + acc[mt][nt][1];
                rowsum[mt * 2 + 1] += acc[mt][nt][2] + acc[mt][nt][3];
            }
#pragma unroll
        for (int r2 = 0; r2 < 4; ++r2) {
            rowsum[r2] += __shfl_xor_sync(0xffffffffu, rowsum[r2], 1);
            rowsum[r2] += __shfl_xor_sync(0xffffffffu, rowsum[r2], 2);
        }
        if ((lane & 3) == 0) {
#pragma unroll
            for (int r2 = 0; r2 < 4; ++r2) {
                int row = wm * 32 + (r2 >> 1) * 16 + (r2 & 1) * 8 + (lane >> 2);
                red_r[row * 2 + wn] = rowsum[r2];
            }
        }

        // colsum (skip on diag): fold the 4 same-column accumulators
        if (i != j) {
#pragma unroll
            for (int nt = 0; nt < 8; ++nt) {
#pragma unroll
                for (int j0 = 0; j0 < 2; ++j0) {
                    float v = acc[0][nt][j0] + acc[0][nt][j0 + 2]
                            + acc[1][nt][j0] + acc[1][nt][j0 + 2];
                    int col = wn * 64 + (nt >> 1) * 16 + (nt & 1) * 8
                            + (lane & 3) * 2 + j0;
                    red_c2[col * 33 + slot] = v;
                }
            }
        }
        __syncthreads();

        if (tid < BM) {
            slice[i * BM + tid] += red_r[tid * 2] + red_r[tid * 2 + 1];
            if (i != j) {
                float s = 0.f;
#pragma unroll
                for (int k = 0; k < 32; ++k) s += red_c2[tid * 33 + k];
                slice[j * BN + tid] += s;
            }
        }

        // advance tile coordinates
        i = ni;
        j = nj;
    }
}

// ---------------------------------------------------------------------------
// Kernel 3a: per-row term = log(sum_slices - e^2) - 2*pos, block-reduced.
// ---------------------------------------------------------------------------
__global__ void __launch_bounds__(512) rowterm2_kernel() {
    const float E2 = 7.38905609893065f;  // exp(2): diagonal of normalized sim
    int tid = threadIdx.x;
    int r = blockIdx.x * 512 + tid;
    float s = 0.f;
#pragma unroll 4
    for (int c = 0; c < NCTA; ++c) s += gx_slice[(size_t)c * NROWS + r];
    float term = logf(s - E2) - 2.0f * gx_pos[r & (BATCH - 1)];
#pragma unroll
    for (int o = 16; o > 0; o >>= 1)
        term += __shfl_xor_sync(0xffffffffu, term, o);
    __shared__ float sh[16];
    if ((tid & 31) == 0) sh[tid >> 5] = term;
    __syncthreads();
    if (tid < 32) {
        float v = (tid < 16) ? sh[tid] : 0.f;
#pragma unroll
        for (int o = 8; o > 0; o >>= 1) v += __shfl_xor_sync(0xffffffffu, v, o);
        if (tid == 0) gx_bsum[blockIdx.x] = v;
    }
}

// ---------------------------------------------------------------------------
// Kernel 3b: final mean from 16 block partials (one warp).
// ---------------------------------------------------------------------------
__global__ void __launch_bounds__(32) meanloss2_kernel(float* __restrict__ out) {
    int lane = threadIdx.x;
    float v = (lane < NRBLK) ? gx_bsum[lane] : 0.f;
#pragma unroll
    for (int o = 8; o > 0; o >>= 1) v += __shfl_xor_sync(0xffffffffu, v, o);
    if (lane == 0) out[0] = v * (1.0f / (float)NROWS);
}

// ---------------------------------------------------------------------------
extern "C" void kernel_launch(void* const* d_in, const int* in_sizes, int n_in,
                              void* d_out, int out_size) {
    const float* p1 = (const float*)d_in[0];
    const float* p2 = (const float*)d_in[1];
    float* out = (float*)d_out;

    l2norm_pos_kernel<<<BATCH / 8, 256>>>(p1, p2);

    cudaFuncSetAttribute((const void*)simexp_tri_kernel,
                         cudaFuncAttributeMaxDynamicSharedMemorySize, SM_TOTAL);
    simexp_tri_kernel<<<NCTA, 256, SM_TOTAL>>>();

    rowterm2_kernel<<<NRBLK, 512>>>();
    meanloss2_kernel<<<1, 32>>>(out);
}